// round 7
// baseline (speedup 1.0000x reference)
#include <cuda_runtime.h>
#include <cuda_bf16.h>

// CRF NLL: out = -(sum_b (score_b - partition_b))
// Shapes fixed by the dataset: B=512, S=1024, T=32 (T == warp size).
//
// NOTE: reference declares tags as jnp.int64, but JAX default (x64 disabled)
// downcasts to int32 — the device buffer is int32. Reading it as long long
// was the R5 illegal-access bug.
//
// Partition: linear-domain forward recurrence with power-of-2 rescaling.
//   alpha_lin(s+1)_j = exp(e_j) * sum_i alpha_lin(s)_i * exp(trans_ij)
// Tracked as p_j * 2^offset with p kept ~O(1) via a per-step scale 2^-k,
// k = exponent(A_0 of previous step) broadcast by shfl (off critical path).
// One log at the end. Mask handled as a per-step select (mask in {0,1}).

#define BB 512
#define SS 1024
#define TT 32
#define PD 8   // prefetch depth (steps)

__device__ float g_partial[BB];

__device__ __forceinline__ float warp_sum(float v) {
#pragma unroll
    for (int o = 16; o; o >>= 1) v += __shfl_xor_sync(0xFFFFFFFFu, v, o);
    return v;
}

__global__ void __launch_bounds__(128, 1) crf_main(
    const float* __restrict__ em, const int* __restrict__ tags,
    const float* __restrict__ mask, const float* __restrict__ trans,
    const float* __restrict__ startt, const float* __restrict__ endt)
{
    __shared__ __align__(16) float sp[4][2][TT];   // p double-buffered per warp
    const int w    = threadIdx.x >> 5;
    const int lane = threadIdx.x & 31;
    const int b    = blockIdx.x * 4 + w;           // one warp == one batch

    // Per-lane column of exp(trans): Mcol[i] = exp(trans[i][lane]). Coalesced.
    float Mcol[TT];
#pragma unroll
    for (int i = 0; i < TT; i++) Mcol[i] = __expf(trans[i * TT + lane]);

    // alpha0 (linear): p = exp(start[j] + em[b,0,j]), offset = 0
    float p = __expf(startt[lane] + em[(size_t)b * SS * TT + lane]);
    sp[w][0][lane] = p;
    __syncwarp();

    // Prefetch pipeline for emissions + mask (steps 1..PD)
    float em_pf[PD], m_pf[PD];
#pragma unroll
    for (int u = 0; u < PD; u++) {
        int s = 1 + u;
        bool ok = s < SS;
        em_pf[u] = ok ? em[((size_t)b * SS + s) * TT + lane] : 0.f;
        m_pf[u]  = ok ? mask[b * SS + s] : 0.f;
    }
    float ex = __expf(em_pf[0]);   // exp(emission) for step 1 (pipelined)
    float av = 1.0f;               // previous step's A_0 (scale source)
    int offset = 0;                // accumulated power-of-2 exponent
    int rb = 0;                    // read buffer index

    // Steps 1..1023 are real; step 1024 is padding with mask forced to 0.
#pragma unroll 1
    for (int s0 = 1; s0 <= SS; s0 += PD) {
#pragma unroll
        for (int u = 0; u < PD; u++) {
            const int s = s0 + u;

            // Scale from stale A_0 (exponent-field trick, no MUFU, off chain)
            unsigned eb   = (__float_as_uint(av) >> 23) & 0xFFu;
            int      k    = (int)eb - 127;
            float scalef  = __uint_as_float((254u - eb) << 23);  // 2^-k
            float emsc    = ex * scalef;
            float m       = m_pf[u];

            // Prefetch step s+PD into slot u (already consumed)
            {
                int sn = s + PD;
                bool ok = sn < SS;
                em_pf[u] = ok ? em[((size_t)b * SS + sn) * TT + lane] : 0.f;
                m_pf[u]  = ok ? mask[b * SS + sn] : 0.f;
            }

            // Matvec: A_lane = sum_i p_i * Mcol[i]  (8x LDS.128 broadcast)
            const float4* pb = (const float4*)sp[w][rb];
            float acc[8];
#pragma unroll
            for (int g = 0; g < 8; g++) {
                float4 v = pb[g];
                acc[g] = fmaf(v.x, Mcol[4 * g + 0],
                         fmaf(v.y, Mcol[4 * g + 1],
                         fmaf(v.z, Mcol[4 * g + 2], v.w * Mcol[4 * g + 3])));
            }
            float A = ((acc[0] + acc[1]) + (acc[2] + acc[3]))
                    + ((acc[4] + acc[5]) + (acc[6] + acc[7]));

            float avn = __shfl_sync(0xFFFFFFFFu, A, 0);  // next step's scale src
            float pn  = A * emsc;
            bool upd  = (m != 0.f);
            p = upd ? pn : p;
            offset += upd ? k : 0;

            sp[w][rb ^ 1][lane] = p;
            __syncwarp();      // orders STS(s) vs LDS(s+1) and LDS(s) vs STS(s+1)
            rb ^= 1;
            av = avn;
            // exp(emission) for step s+1, computed a step early (off chain)
            ex = __expf(em_pf[(u + 1) & (PD - 1)]);
        }
    }

    // partition_b = ln(sum_j p_j * exp(end_j)) + offset * ln2
    float val = p * __expf(endt[lane]);
    val = warp_sum(val);
    float partition = logf(val) + (float)offset * 0.6931471805599453f;

    // ---- score (gold-path score), lanes strided over sequence positions ----
    float sc = 0.f, msum = 0.f;
    const int* tg = tags + (size_t)b * SS;
#pragma unroll 4
    for (int it = 0; it < SS / 32; it++) {
        int s  = it * 32 + lane;
        int tc = tg[s];
        float mm = mask[b * SS + s];
        msum += mm;
        if (s == 0) {
            sc += startt[tc] + em[(size_t)b * SS * TT + tc];
        } else {
            int tp = tg[s - 1];
            sc += (em[((size_t)b * SS + s) * TT + tc] + trans[tp * TT + tc]) * mm;
        }
    }
    sc   = warp_sum(sc);
    msum = warp_sum(msum);

    if (lane == 0) {
        int last = (int)msum - 1;
        int lt   = tg[last];
        g_partial[b] = (sc + endt[lt]) - partition;
    }
}

__global__ void crf_reduce(float* __restrict__ out) {
    __shared__ float sh[16];
    int t = threadIdx.x;           // 512 threads
    float v = g_partial[t];
    v = warp_sum(v);
    if ((t & 31) == 0) sh[t >> 5] = v;
    __syncthreads();
    if (t < 32) {
        float x = (t < 16) ? sh[t] : 0.f;
        x = warp_sum(x);
        if (t == 0) out[0] = -x;
    }
}

extern "C" void kernel_launch(void* const* d_in, const int* in_sizes, int n_in,
                              void* d_out, int out_size) {
    const float* em    = (const float*)d_in[0];
    const int*   tags  = (const int*)d_in[1];
    const float* mask  = (const float*)d_in[2];
    const float* trans = (const float*)d_in[3];
    const float* st    = (const float*)d_in[4];
    const float* en    = (const float*)d_in[5];
    (void)in_sizes; (void)n_in; (void)out_size;

    crf_main<<<BB / 4, 128>>>(em, tags, mask, trans, st, en);
    crf_reduce<<<1, BB>>>((float*)d_out);
}